// round 2
// baseline (speedup 1.0000x reference)
#include <cuda_runtime.h>
#include <cstdint>
#include <cstddef>

#define BB 512
#define TT 512
#define FF 13
#define HH 128

// 134 MB scratch for the precomputed input projection xp[b][t][h]
static __device__ float g_xp[(size_t)BB * TT * HH];

typedef unsigned long long u64;

__device__ __forceinline__ u64 f2fma(u64 a, u64 b, u64 c) {
    u64 d;
    asm("fma.rn.f32x2 %0, %1, %2, %3;" : "=l"(d) : "l"(a), "l"(b), "l"(c));
    return d;
}
__device__ __forceinline__ float f2sum(u64 v) {
    float lo, hi;
    asm("mov.b64 {%0,%1}, %2;" : "=f"(lo), "=f"(hi) : "l"(v));
    return lo + hi;
}
__device__ __forceinline__ float fast_tanh(float x) {
    // tanh(x) = 1 - 2/(e^{2x}+1); graceful at +-inf via __expf saturation
    float e = __expf(2.f * x);
    return 1.f - 2.f / (e + 1.f);
}
__device__ __forceinline__ float fast_sigmoid(float x) {
    return 1.f / (1.f + __expf(-x));
}

// ---------------------------------------------------------------------------
// Kernel 1: xp[b][t][h] = sum_f x[b][t][f] * W_ih[h][f] + b_ih[h] + b_hh[h]
// One block per batch row; x rows staged through smem in 64-timestep chunks.
// ---------------------------------------------------------------------------
__global__ void __launch_bounds__(256)
xp_kernel(const float* __restrict__ x,
          const float* __restrict__ W_ih,
          const float* __restrict__ b_ih,
          const float* __restrict__ b_hh) {
    const int b   = blockIdx.x;
    const int tid = threadIdx.x;
    const int h   = tid & (HH - 1);
    const int th  = tid >> 7;  // 0..1

    float wih[FF];
#pragma unroll
    for (int f = 0; f < FF; f++) wih[f] = W_ih[h * FF + f];
    const float bias = b_ih[h] + b_hh[h];

    __shared__ float xs[64 * FF];
    const float* xrow  = x + (size_t)b * TT * FF;
    float*       xprow = g_xp + (size_t)b * TT * HH;

    for (int t0 = 0; t0 < TT; t0 += 64) {
        __syncthreads();
        const float* src = xrow + (size_t)t0 * FF;
        for (int idx = tid; idx < 64 * FF; idx += 256) xs[idx] = src[idx];
        __syncthreads();
#pragma unroll 4
        for (int q = 0; q < 32; q++) {
            const int tloc = th * 32 + q;
            float acc = bias;
#pragma unroll
            for (int f = 0; f < FF; f++) acc += xs[tloc * FF + f] * wih[f];
            xprow[(size_t)(t0 + tloc) * HH + h] = acc;
        }
    }
}

// ---------------------------------------------------------------------------
// Kernel 2: persistent per-block recurrence over T=512 steps for 4 batch rows,
// fused with fc1(relu) + fc2(sigmoid) head. Weights in registers, h in smem.
//
// Thread roles (256 threads):
//   recurrent: j = tid>>1 (output unit), kh = tid&1 (k half), pair via shfl^1
//   fc:        o = tid>>2, ip = (tid>>1)&1 (batch-row pair), kh2 = tid&1
// ---------------------------------------------------------------------------
__global__ void __launch_bounds__(256, 1)
rnn_kernel(const float* __restrict__ W_hh,
           const float* __restrict__ fc1_w,
           const float* __restrict__ fc1_b,
           const float* __restrict__ fc2_w,
           const float* __restrict__ fc2_b,
           float* __restrict__ out) {
    const int tid = threadIdx.x;
    const int b0  = blockIdx.x * 4;

    const int j     = tid >> 1;
    const int kh    = tid & 1;
    const int kbase = kh * 64;

    const int o      = tid >> 2;
    const int sub    = tid & 3;
    const int ip     = sub >> 1;
    const int kbase2 = (sub & 1) * 64;

    __shared__ __align__(16) float h_rows[4][HH];  // h[i][k]
    __shared__ float part[8][4];                   // per-warp fc2 partials

    // W_hh[j][kbase..kbase+63] packed as 32 f32x2 registers
    u64 w2[32];
    {
        const u64* wr = (const u64*)(W_hh + j * HH + kbase);
#pragma unroll
        for (int m = 0; m < 32; m++) w2[m] = wr[m];
    }
    // fc1_w[o][kbase2..kbase2+63] packed as 32 f32x2 registers
    u64 fw2[32];
    {
        const u64* fr = (const u64*)(fc1_w + o * HH + kbase2);
#pragma unroll
        for (int m = 0; m < 32; m++) fw2[m] = fr[m];
    }
    const float f1b = fc1_b[o];
    const float f2w = fc2_w[o];
    const float f2b = fc2_b[0];

    for (int idx = tid; idx < 4 * HH; idx += 256) (&h_rows[0][0])[idx] = 0.f;
    __syncthreads();

    // prefetch xp for t=0 (kh==0 threads own xp[i][t][j])
    float xp_cur[4];
    if (kh == 0) {
#pragma unroll
        for (int i = 0; i < 4; i++)
            xp_cur[i] = g_xp[((size_t)(b0 + i) * TT + 0) * HH + j];
    }

    const unsigned FULL = 0xffffffffu;
    const int lane = tid & 31;
    const int wrp  = tid >> 5;

    for (int t = 0; t < TT; t++) {
        // prefetch next timestep's xp (latency hidden behind this step)
        float xp_nxt[4];
        if (kh == 0) {
            const int tn = (t + 1 < TT) ? (t + 1) : t;
#pragma unroll
            for (int i = 0; i < 4; i++)
                xp_nxt[i] = g_xp[((size_t)(b0 + i) * TT + tn) * HH + j];
        }

        // ---- recurrent: s[i] = sum_k h[i][k] * W_hh[j][k] (this k-half) ----
        float s[4];
#pragma unroll
        for (int i = 0; i < 4; i++) {
            u64 acc = 0ull;
            const ulonglong2* hr = (const ulonglong2*)(&h_rows[i][kbase]);
#pragma unroll
            for (int m = 0; m < 16; m++) {
                ulonglong2 hv = hr[m];
                acc = f2fma(hv.x, w2[2 * m], acc);
                acc = f2fma(hv.y, w2[2 * m + 1], acc);
            }
            float ss = f2sum(acc);
            ss += __shfl_xor_sync(FULL, ss, 1);  // combine k halves
            s[i] = ss;
        }
        float hn[4];
        if (kh == 0) {
#pragma unroll
            for (int i = 0; i < 4; i++) hn[i] = fast_tanh(xp_cur[i] + s[i]);
        }
        __syncthreads();  // all reads of h_{t-1} complete
        if (kh == 0) {
#pragma unroll
            for (int i = 0; i < 4; i++) h_rows[i][j] = hn[i];
        }
        __syncthreads();  // h_t visible to all

        // ---- fc1 + relu + fc2 weight ----
        float y[2];
#pragma unroll
        for (int u = 0; u < 2; u++) {
            const int i = 2 * ip + u;
            u64 acc = 0ull;
            const ulonglong2* hr = (const ulonglong2*)(&h_rows[i][kbase2]);
#pragma unroll
            for (int m = 0; m < 16; m++) {
                ulonglong2 hv = hr[m];
                acc = f2fma(hv.x, fw2[2 * m], acc);
                acc = f2fma(hv.y, fw2[2 * m + 1], acc);
            }
            float ss = f2sum(acc);
            ss += __shfl_xor_sync(FULL, ss, 1);  // combine k halves
            y[u] = fmaxf(ss + f1b, 0.f) * f2w;
        }
        // reduce over the 8 o's in this warp (lanes sharing tid&3)
#pragma unroll
        for (int msk = 4; msk <= 16; msk <<= 1) {
            y[0] += __shfl_xor_sync(FULL, y[0], msk);
            y[1] += __shfl_xor_sync(FULL, y[1], msk);
        }
        if (lane == 0)      { part[wrp][0] = y[0]; part[wrp][1] = y[1]; }
        else if (lane == 2) { part[wrp][2] = y[0]; part[wrp][3] = y[1]; }
        __syncthreads();
        if (tid < 4) {
            float acc = f2b;
#pragma unroll
            for (int w = 0; w < 8; w++) acc += part[w][tid];
            out[(size_t)(b0 + tid) * TT + t] = fast_sigmoid(acc);
        }
#pragma unroll
        for (int i = 0; i < 4; i++) xp_cur[i] = xp_nxt[i];
    }
}

extern "C" void kernel_launch(void* const* d_in, const int* in_sizes, int n_in,
                              void* d_out, int out_size) {
    const float* x     = (const float*)d_in[0];
    const float* W_ih  = (const float*)d_in[1];
    const float* W_hh  = (const float*)d_in[2];
    const float* b_ih  = (const float*)d_in[3];
    const float* b_hh  = (const float*)d_in[4];
    const float* fc1_w = (const float*)d_in[5];
    const float* fc1_b = (const float*)d_in[6];
    const float* fc2_w = (const float*)d_in[7];
    const float* fc2_b = (const float*)d_in[8];
    float* out = (float*)d_out;

    xp_kernel<<<BB, 256>>>(x, W_ih, b_ih, b_hh);
    rnn_kernel<<<BB / 4, 256>>>(W_hh, fc1_w, fc1_b, fc2_w, fc2_b, out);
}

// round 3
// speedup vs baseline: 2.5377x; 2.5377x over previous
#include <cuda_runtime.h>
#include <cstdint>
#include <cstddef>

#define BB 512
#define TT 512
#define FF 13
#define HH 128

// scratch: input projection xp[b][t][h] and hidden states hs[b][t][h]
static __device__ float g_xp[(size_t)BB * TT * HH];
static __device__ float g_hs[(size_t)BB * TT * HH];

typedef unsigned long long u64;

__device__ __forceinline__ u64 f2fma(u64 a, u64 b, u64 c) {
    u64 d;
    asm("fma.rn.f32x2 %0, %1, %2, %3;" : "=l"(d) : "l"(a), "l"(b), "l"(c));
    return d;
}
__device__ __forceinline__ float f2sum(u64 v) {
    float lo, hi;
    asm("mov.b64 {%0,%1}, %2;" : "=f"(lo), "=f"(hi) : "l"(v));
    return lo + hi;
}
__device__ __forceinline__ float fast_tanh(float x) {
    float e = __expf(2.f * x);
    return 1.f - 2.f / (e + 1.f);
}
__device__ __forceinline__ float fast_sigmoid(float x) {
    return 1.f / (1.f + __expf(-x));
}

// ---------------------------------------------------------------------------
// Kernel 1: xp[b][t][h] = x[b][t]·W_ih[h] + b_ih[h] + b_hh[h]
// ---------------------------------------------------------------------------
__global__ void __launch_bounds__(256)
xp_kernel(const float* __restrict__ x,
          const float* __restrict__ W_ih,
          const float* __restrict__ b_ih,
          const float* __restrict__ b_hh) {
    const int b   = blockIdx.x;
    const int tid = threadIdx.x;
    const int h   = tid & (HH - 1);
    const int th  = tid >> 7;

    float wih[FF];
#pragma unroll
    for (int f = 0; f < FF; f++) wih[f] = W_ih[h * FF + f];
    const float bias = b_ih[h] + b_hh[h];

    __shared__ float xs[64 * FF];
    const float* xrow  = x + (size_t)b * TT * FF;
    float*       xprow = g_xp + (size_t)b * TT * HH;

    for (int t0 = 0; t0 < TT; t0 += 64) {
        __syncthreads();
        const float* src = xrow + (size_t)t0 * FF;
        for (int idx = tid; idx < 64 * FF; idx += 256) xs[idx] = src[idx];
        __syncthreads();
#pragma unroll 4
        for (int q = 0; q < 32; q++) {
            const int tloc = th * 32 + q;
            float acc = bias;
#pragma unroll
            for (int f = 0; f < FF; f++) acc += xs[tloc * FF + f] * wih[f];
            xprow[(size_t)(t0 + tloc) * HH + h] = acc;
        }
    }
}

// ---------------------------------------------------------------------------
// Kernel 2: recurrence only. 128 blocks x 256 threads, 4 batch rows/block.
// Thread layout: warp = rp(2 rows-pairs) x jh(4);  lane = kq*8 + jlo.
//   each thread: J=4 outputs (j = (jh*8+jlo)*4 + 0..3), k-quarter kq (32 k),
//   2 rows (rp*2, rp*2+1). Weights 4x32 floats in 128 registers.
// LDS reads are pure 8-lane-phase broadcast; kq combined via shfl_xor(8,16).
// h_t streamed to g_hs for the separate fc kernel.
// ---------------------------------------------------------------------------
__global__ void __launch_bounds__(256, 1)
rnn_kernel(const float* __restrict__ W_hh, float* __restrict__ unused) {
    const int tid  = threadIdx.x;
    const int warp = tid >> 5;
    const int lane = tid & 31;
    const int rp   = warp >> 2;        // 0,1 -> rows {0,1} / {2,3}
    const int jh   = warp & 3;         // 0..3
    const int jlo  = lane & 7;         // 0..7
    const int kq   = lane >> 3;        // 0..3
    const int k0   = kq * 32;
    const int jb   = jh * 8 + jlo;     // 0..31
    const int j0   = jb * 4;
    const int b0   = blockIdx.x * 4;
    const int r0   = rp * 2;

    __shared__ __align__(16) float h_rows[4][HH];

    // weights: 4 j-rows x 32 k (this quarter) = 64 u64 = 128 regs
    u64 w2[4][16];
#pragma unroll
    for (int jj = 0; jj < 4; jj++) {
        const u64* wr = (const u64*)(W_hh + (j0 + jj) * HH + k0);
#pragma unroll
        for (int m = 0; m < 16; m++) w2[jj][m] = wr[m];
    }

    for (int idx = tid; idx < 4 * HH; idx += 256) (&h_rows[0][0])[idx] = 0.f;
    __syncthreads();

    // this thread finalizes j = j0 + kq for its 2 rows
    const int jmine = j0 + kq;
    float xp_cur[2];
#pragma unroll
    for (int ii = 0; ii < 2; ii++)
        xp_cur[ii] = g_xp[((size_t)(b0 + r0 + ii) * TT + 0) * HH + jmine];

    const unsigned FULL = 0xffffffffu;

    for (int t = 0; t < TT; t++) {
        // prefetch next xp
        float xp_nxt[2];
        {
            const int tn = (t + 1 < TT) ? (t + 1) : t;
#pragma unroll
            for (int ii = 0; ii < 2; ii++)
                xp_nxt[ii] = g_xp[((size_t)(b0 + r0 + ii) * TT + tn) * HH + jmine];
        }

        u64 acc0[4], acc1[4];
#pragma unroll
        for (int jj = 0; jj < 4; jj++) { acc0[jj] = 0ull; acc1[jj] = 0ull; }

        const ulonglong2* hr0 = (const ulonglong2*)(&h_rows[r0 + 0][k0]);
        const ulonglong2* hr1 = (const ulonglong2*)(&h_rows[r0 + 1][k0]);
#pragma unroll
        for (int m = 0; m < 8; m++) {
            ulonglong2 hv0 = hr0[m];
            ulonglong2 hv1 = hr1[m];
#pragma unroll
            for (int jj = 0; jj < 4; jj++) {
                acc0[jj] = f2fma(hv0.x, w2[jj][2 * m],     acc0[jj]);
                acc0[jj] = f2fma(hv0.y, w2[jj][2 * m + 1], acc0[jj]);
                acc1[jj] = f2fma(hv1.x, w2[jj][2 * m],     acc1[jj]);
                acc1[jj] = f2fma(hv1.y, w2[jj][2 * m + 1], acc1[jj]);
            }
        }

        // combine over the 4 k-quarters (lanes differ in bits 3,4)
        float s0[4], s1[4];
#pragma unroll
        for (int jj = 0; jj < 4; jj++) {
            float a = f2sum(acc0[jj]);
            a += __shfl_xor_sync(FULL, a, 8);
            a += __shfl_xor_sync(FULL, a, 16);
            s0[jj] = a;
            float b = f2sum(acc1[jj]);
            b += __shfl_xor_sync(FULL, b, 8);
            b += __shfl_xor_sync(FULL, b, 16);
            s1[jj] = b;
        }
        // each lane finalizes jj == kq (values identical across kq lanes)
        float sm0 = s0[0], sm1 = s1[0];
#pragma unroll
        for (int jj = 1; jj < 4; jj++) {
            if (jj == kq) { sm0 = s0[jj]; sm1 = s1[jj]; }
        }
        const float hn0 = fast_tanh(xp_cur[0] + sm0);
        const float hn1 = fast_tanh(xp_cur[1] + sm1);

        __syncthreads();  // all reads of h_{t-1} done
        h_rows[r0 + 0][jmine] = hn0;
        h_rows[r0 + 1][jmine] = hn1;
        g_hs[((size_t)(b0 + r0 + 0) * TT + t) * HH + jmine] = hn0;
        g_hs[((size_t)(b0 + r0 + 1) * TT + t) * HH + jmine] = hn1;
        __syncthreads();  // h_t visible

        xp_cur[0] = xp_nxt[0];
        xp_cur[1] = xp_nxt[1];
    }
}

// ---------------------------------------------------------------------------
// Kernel 3: fc head over all 512x512 positions.
//   y[p] = sigmoid(fc2_b + sum_o fc2_w[o]*relu(fc1_w[o]·h[p] + fc1_b[o]))
// Block: 256 threads, 256 positions. Tile 16 positions into smem.
// Warp = (pt 0..3, olh 0..1); lane = kq*8 + ol8. Each thread: 4 o's
// (o = ol8 + 8*oo + 32*olh), k-quarter kq. Weights 4x32 floats in regs.
// ---------------------------------------------------------------------------
__global__ void __launch_bounds__(256, 1)
fc_kernel(const float* __restrict__ fc1_w,
          const float* __restrict__ fc1_b,
          const float* __restrict__ fc2_w,
          const float* __restrict__ fc2_b,
          float* __restrict__ out) {
    const int tid  = threadIdx.x;
    const int warp = tid >> 5;
    const int lane = tid & 31;
    const int pt   = warp >> 1;      // position within quad
    const int olh  = warp & 1;       // o high-half
    const int ol8  = lane & 7;
    const int kq   = lane >> 3;
    const int k0   = kq * 32;

    // weights: o = ol8 + 8*oo + 32*olh, k-quarter
    u64 fw2[4][16];
    float f1b[4], f2w[4];
#pragma unroll
    for (int oo = 0; oo < 4; oo++) {
        const int o = ol8 + 8 * oo + 32 * olh;
        const u64* fr = (const u64*)(fc1_w + o * HH + k0);
#pragma unroll
        for (int m = 0; m < 16; m++) fw2[oo][m] = fr[m];
        f1b[oo] = fc1_b[o];
        f2w[oo] = fc2_w[o];
    }
    const float f2b = fc2_b[0];

    __shared__ __align__(16) float htile[16][HH];
    __shared__ float part[16][2];

    const unsigned FULL = 0xffffffffu;
    const size_t pos_base_blk = (size_t)blockIdx.x * 256;

    for (int tile = 0; tile < 16; tile++) {
        const size_t pos0 = pos_base_blk + tile * 16;
        __syncthreads();  // protect htile/part reuse
        // stage 16 positions (8KB), coalesced
        {
            const float4* src = (const float4*)(g_hs + pos0 * HH);
            float4* dst = (float4*)(&htile[0][0]);
            for (int idx = tid; idx < 16 * HH / 4; idx += 256) dst[idx] = src[idx];
        }
        __syncthreads();

#pragma unroll
        for (int pass = 0; pass < 4; pass++) {
            const int p = pass * 4 + pt;
            const ulonglong2* hr = (const ulonglong2*)(&htile[p][k0]);
            u64 acc[4];
#pragma unroll
            for (int oo = 0; oo < 4; oo++) acc[oo] = 0ull;
#pragma unroll
            for (int m = 0; m < 8; m++) {
                ulonglong2 hv = hr[m];
#pragma unroll
                for (int oo = 0; oo < 4; oo++) {
                    acc[oo] = f2fma(hv.x, fw2[oo][2 * m],     acc[oo]);
                    acc[oo] = f2fma(hv.y, fw2[oo][2 * m + 1], acc[oo]);
                }
            }
            float y = 0.f;
#pragma unroll
            for (int oo = 0; oo < 4; oo++) {
                float s = f2sum(acc[oo]);
                s += __shfl_xor_sync(FULL, s, 8);
                s += __shfl_xor_sync(FULL, s, 16);
                y += f2w[oo] * fmaxf(s + f1b[oo], 0.f);
            }
            // reduce over ol8
            y += __shfl_xor_sync(FULL, y, 1);
            y += __shfl_xor_sync(FULL, y, 2);
            y += __shfl_xor_sync(FULL, y, 4);
            if (lane == 0) part[p][olh] = y;
        }
        __syncthreads();
        if (tid < 16) {
            out[pos0 + tid] = fast_sigmoid(part[tid][0] + part[tid][1] + f2b);
        }
    }
}

extern "C" void kernel_launch(void* const* d_in, const int* in_sizes, int n_in,
                              void* d_out, int out_size) {
    const float* x     = (const float*)d_in[0];
    const float* W_ih  = (const float*)d_in[1];
    const float* W_hh  = (const float*)d_in[2];
    const float* b_ih  = (const float*)d_in[3];
    const float* b_hh  = (const float*)d_in[4];
    const float* fc1_w = (const float*)d_in[5];
    const float* fc1_b = (const float*)d_in[6];
    const float* fc2_w = (const float*)d_in[7];
    const float* fc2_b = (const float*)d_in[8];
    float* out = (float*)d_out;

    xp_kernel<<<BB, 256>>>(x, W_ih, b_ih, b_hh);
    rnn_kernel<<<BB / 4, 256>>>(W_hh, out);
    fc_kernel<<<(BB * TT) / 256, 256>>>(fc1_w, fc1_b, fc2_w, fc2_b, out);
}